// round 13
// baseline (speedup 1.0000x reference)
#include <cuda_runtime.h>
#include <cuda_bf16.h>
#include <cuda_fp16.h>

#define B_    32
#define N_    500
#define NV_   400
#define HIN_  64
#define HID_  16
#define NH_   8
#define HC_   128   // NH*HID
#define CAP_  96
#define STR2_ 34    // padded stride for 32-row transposed x tile (even => 8B aligned)
#define NEG_INF_ -1e20f
#define FULLM 0xffffffffu

// ---------------- scratch (device globals; 16B-aligned) --------------------
__device__ __align__(16) __half g_h1h [B_*N_*HC_];   // layer-1 proj, fp16 [bn][128]
__device__ float g_es1  [B_*NH_*N_];
__device__ float g_ed1  [B_*NH_*N_];
__device__ __align__(16) __half g_h2h [B_*N_*HIN_];  // fp16 [bn][64]
__device__ float g_es2  [B_*N_];
__device__ float g_ed2  [B_*N_];
__device__ __align__(16) float g_xc   [B_*N_*HIN_];  // fp32 [bn][64]
__device__ float g_s0   [B_*N_];                     // xc . attn_w[0:64]
__device__ unsigned short g_nidx[B_*N_*CAP_];
__device__ int            g_nnz [B_*N_];

// ---------------- kernel 0: layer-1 tiled projection (standalone) ----------
// 500 blocks x 256 threads; block = 32 rows x 128 cols; thread = 2x8 tile.
__global__ __launch_bounds__(256) void k_proj1(
    const float* __restrict__ x, const float* __restrict__ w1,
    const float* __restrict__ a_src1, const float* __restrict__ a_dst1)
{
    __shared__ __align__(16) float xt[HIN_ * STR2_];   // ~8.7KB
    int t = threadIdx.x;
    int gbase = blockIdx.x * 32;

    for (int i = t; i < 512; i += 256) {       // 32 rows x 16 float4, transposed
        int row = i >> 4, fg = (i & 15) << 2;
        float4 v = *(const float4*)(x + (size_t)(gbase + row) * HIN_ + fg);
        xt[(fg+0)*STR2_ + row] = v.x; xt[(fg+1)*STR2_ + row] = v.y;
        xt[(fg+2)*STR2_ + row] = v.z; xt[(fg+3)*STR2_ + row] = v.w;
    }
    __syncthreads();

    int rt = t >> 4, ct = t & 15;              // rows rt*2.., cols ct*8..
    int h = ct >> 1, obase = (ct & 1) << 3;
    const float* wb = w1 + (h << 10) + obase;  // w1[h][f][o], stride 16 per f

    float acc[2][8];
#pragma unroll
    for (int a = 0; a < 2; a++)
#pragma unroll
        for (int c = 0; c < 8; c++) acc[a][c] = 0.f;

#pragma unroll 4
    for (int f = 0; f < HIN_; f++) {
        float2 xv = *(float2*)&xt[f*STR2_ + rt*2];
        float4 w0 = __ldg((const float4*)(wb + (f << 4)));
        float4 w1v= __ldg((const float4*)(wb + (f << 4) + 4));
        float wr[8] = {w0.x,w0.y,w0.z,w0.w,w1v.x,w1v.y,w1v.z,w1v.w};
#pragma unroll
        for (int c = 0; c < 8; c++) {
            acc[0][c] += xv.x * wr[c];
            acc[1][c] += xv.y * wr[c];
        }
    }

    float as[8], ad[8];
#pragma unroll
    for (int c = 0; c < 8; c++) {
        as[c] = __ldg(a_src1 + h*HID_ + obase + c);
        ad[c] = __ldg(a_dst1 + h*HID_ + obase + c);
    }
#pragma unroll
    for (int rr = 0; rr < 2; rr++) {
        int gr = gbase + rt*2 + rr;
        int b = gr / N_, n = gr % N_;
        __align__(16) __half2 hp[4];
        hp[0] = __floats2half2_rn(acc[rr][0], acc[rr][1]);
        hp[1] = __floats2half2_rn(acc[rr][2], acc[rr][3]);
        hp[2] = __floats2half2_rn(acc[rr][4], acc[rr][5]);
        hp[3] = __floats2half2_rn(acc[rr][6], acc[rr][7]);
        *(uint4*)(g_h1h + (size_t)gr * HC_ + ct*8) = *(uint4*)hp;
        float ps = 0.f, pd = 0.f;
#pragma unroll
        for (int c = 0; c < 8; c++) { ps += acc[rr][c]*as[c]; pd += acc[rr][c]*ad[c]; }
        ps += __shfl_xor_sync(FULLM, ps, 1);
        pd += __shfl_xor_sync(FULLM, pd, 1);
        if ((ct & 1) == 0) {
            g_es1[(b*NH_ + h) * N_ + n] = ps;
            g_ed1[(b*NH_ + h) * N_ + n] = pd;
        }
    }
}

// ---------------- kernel 1: row compaction + attn1 + ELU + proj2 -----------
// 16000 blocks x 256 threads. Block start: 4-warp parallel ordered ballot
// compaction of this row's A (replaces the standalone compaction kernel;
// bit-identical index list). Then attn1 / ELU / matvec as before.
__global__ __launch_bounds__(256) void k_attn1proj2(
    const float* __restrict__ A, const float* __restrict__ w2,
    const float* __restrict__ a_src2, const float* __restrict__ a_dst2)
{
    int bn = blockIdx.x;
    int b = bn / N_, i = bn % N_;
    __shared__ __align__(16) float red[8][HC_];
    __shared__ __align__(16) float sp[NH_][CAP_];
    __shared__ __align__(16) float hcat[HC_];
    __shared__ __align__(16) float h2s[HIN_];
    __shared__ int   snj[CAP_];
    __shared__ float sinv[NH_];
    __shared__ int   wcnt[4];
    __shared__ int   snnz;
    int t = threadIdx.x, h = t >> 5, lane = t & 31;

    // ---- compaction: warp r scans row quarter r (125 float4 total) --------
    unsigned m4 = 0; int excl = 0;
    if (h < 4) {
        int q = h * 32 + lane;
        float4 v = (q < 125) ? __ldg((const float4*)(A + (size_t)bn * N_) + q)
                             : make_float4(0.f, 0.f, 0.f, 0.f);
        m4 = (v.x > 0.f) | ((v.y > 0.f) << 1) | ((v.z > 0.f) << 2) | ((v.w > 0.f) << 3);
        if (q >= 125) m4 = 0;
        int c4 = __popc(m4);
        int inc = c4;
#pragma unroll
        for (int off = 1; off < 32; off <<= 1) {
            int nb = __shfl_up_sync(FULLM, inc, off);
            if (lane >= off) inc += nb;
        }
        excl = inc - c4;
        if (lane == 31) wcnt[h] = inc;
    }
    __syncthreads();
    if (h < 4) {
        int off = 0;
#pragma unroll
        for (int r = 0; r < 4; r++) if (r < h) off += wcnt[r];
        int basej = (h * 32 + lane) << 2;
#pragma unroll
        for (int e = 0; e < 4; e++)
            if (m4 & (1u << e)) {
                int pos = off + excl + __popc(m4 & ((1u << e) - 1u));
                if (pos < CAP_) snj[pos] = basej + e;
            }
    }
    if (t == 0) {
        int s = wcnt[0] + wcnt[1] + wcnt[2] + wcnt[3];
        snnz = (s < CAP_) ? s : CAP_;
    }
    __syncthreads();
    int nnz = snnz;

    // persist the list for k_attn2 (coalesced small writes)
    if (t < nnz) g_nidx[(size_t)bn * CAP_ + t] = (unsigned short)snj[t];
    if (t == 0)  g_nnz[bn] = nnz;

    // ---- phase 1: per-head unnormalized softmax weights (|e| small) -------
    float es = g_es1[(b*NH_ + h) * N_ + i];
    const float* ed = g_ed1 + (b*NH_ + h) * N_;
    float sum = 0.f;
    for (int k = lane; k < nnz; k += 32) {
        float e = es + ed[snj[k]];
        e = (e > 0.f) ? e : 0.2f * e;
        float p = __expf(e);
        sp[h][k] = p;
        sum += p;
    }
#pragma unroll
    for (int off = 16; off; off >>= 1) sum += __shfl_xor_sync(FULLM, sum, off);
    if (lane == 0) sinv[h] = 1.f / sum;
    __syncthreads();

    // ---- phase 2: slice = warp, q4 = 4-channel group; fp16 gathers --------
    int slice = t >> 5, q4 = (t & 31) << 2, hh = q4 >> 4;
    const __half* base = g_h1h + (size_t)b * N_ * HC_ + q4;
    float4 acc = make_float4(0.f, 0.f, 0.f, 0.f);
    for (int k = slice; k < nnz; k += 8) {
        float w = sp[hh][k];
        uint2 u = *(const uint2*)(base + (size_t)snj[k] * HC_);
        float2 f0 = __half22float2(*(__half2*)&u.x);
        float2 f1 = __half22float2(*(__half2*)&u.y);
        acc.x += w*f0.x; acc.y += w*f0.y; acc.z += w*f1.x; acc.w += w*f1.y;
    }
    *(float4*)&red[slice][q4] = acc;
    __syncthreads();

    if (t < HC_) {
        float s = 0.f;
#pragma unroll
        for (int s8 = 0; s8 < 8; s8++) s += red[s8][t];
        float v = s * sinv[t >> 4];
        v = (v > 0.f) ? v : (__expf(v) - 1.f);   // ELU
        hcat[t] = v;
    }
    __syncthreads();

    // ---- phase 3: matvec h2[o] = sum_f hcat[f]*w2[f][o] -------------------
    {
        int o = t & 63, g = t >> 6;
        const float* wv = w2 + (g << 5) * HIN_ + o;
        float a2 = 0.f;
#pragma unroll 8
        for (int f = 0; f < 32; f++) a2 += hcat[(g << 5) + f] * wv[f * HIN_];
        red[g][o] = a2;
    }
    __syncthreads();
    if (t < HIN_) {
        float hv = red[0][t] + red[1][t] + red[2][t] + red[3][t];
        h2s[t] = hv;
        g_h2h[(size_t)bn * HIN_ + t] = __float2half_rn(hv);
    }
    __syncthreads();
    if (t < 32) {
        float v0 = h2s[t], v1 = h2s[t + 32];
        float ps = v0 * __ldg(a_src2 + t) + v1 * __ldg(a_src2 + t + 32);
        float pd = v0 * __ldg(a_dst2 + t) + v1 * __ldg(a_dst2 + t + 32);
#pragma unroll
        for (int off = 16; off; off >>= 1) {
            ps += __shfl_xor_sync(FULLM, ps, off);
            pd += __shfl_xor_sync(FULLM, pd, off);
        }
        if (t == 0) { g_es2[bn] = ps; g_ed2[bn] = pd; }
    }
}

// ---------------- kernel 2: layer-2 attention + score dot ------------------
// 2000 blocks x 256 threads; warp per row. No smem/barriers. fp16 gathers.
__global__ __launch_bounds__(256) void k_attn2(const float* __restrict__ aw)
{
    int wid = threadIdx.x >> 5, lane = threadIdx.x & 31;
    int bn = blockIdx.x * 8 + wid;
    int b = bn / N_, i = bn % N_;

    if (i >= NV_) {                          // padded node: zero row + score
        if (lane < 16)
            *(float4*)(g_xc + (size_t)bn * HIN_ + lane*4) =
                make_float4(0.f, 0.f, 0.f, 0.f);
        if (lane == 0) g_s0[bn] = 0.f;
        return;
    }

    int nnz = g_nnz[bn];
    const unsigned short* nidx = g_nidx + (size_t)bn * CAP_;
    int idx0 = (lane      < nnz) ? nidx[lane]      : 0;
    int idx1 = (lane + 32 < nnz) ? nidx[lane + 32] : 0;
    int idx2 = (lane + 64 < nnz) ? nidx[lane + 64] : 0;

    float es = g_es2[bn];
    const float* ed = g_ed2 + b * N_;
    float p0 = 0.f, p1 = 0.f, p2 = 0.f;
    if (lane < nnz)      { float e = es + ed[idx0]; e = (e>0.f)?e:0.2f*e; p0 = __expf(e); }
    if (lane + 32 < nnz) { float e = es + ed[idx1]; e = (e>0.f)?e:0.2f*e; p1 = __expf(e); }
    if (lane + 64 < nnz) { float e = es + ed[idx2]; e = (e>0.f)?e:0.2f*e; p2 = __expf(e); }
    float sum = p0 + p1 + p2;
#pragma unroll
    for (int off = 16; off; off >>= 1) sum += __shfl_xor_sync(FULLM, sum, off);
    float inv = 1.f / sum;

    // gather: lane = slice(0..1) x c16(0..15); warp covers all 64 channels
    int slice = lane >> 4, c16 = lane & 15;
    const __half* base = g_h2h + (size_t)b * N_ * HIN_ + c16 * 4;
    float4 acc = make_float4(0.f, 0.f, 0.f, 0.f);
    int mcnt = (nnz + 1) >> 1;
#pragma unroll 4
    for (int m = 0; m < mcnt; m++) {
        int k = slice + (m << 1);
        int ri = (m >> 4);                    // (2m+slice)>>5 — warp-uniform
        float ps = (ri == 0) ? p0 : ((ri == 1) ? p1 : p2);
        int   is = (ri == 0) ? idx0 : ((ri == 1) ? idx1 : idx2);
        float pv = __shfl_sync(FULLM, ps, k & 31);
        int   jj = __shfl_sync(FULLM, is, k & 31);
        if (k < nnz) {
            uint2 u = *(const uint2*)(base + (size_t)jj * HIN_);
            float2 f0 = __half22float2(*(__half2*)&u.x);
            float2 f1 = __half22float2(*(__half2*)&u.y);
            acc.x += pv*f0.x; acc.y += pv*f0.y; acc.z += pv*f1.x; acc.w += pv*f1.y;
        }
    }
    acc.x += __shfl_xor_sync(FULLM, acc.x, 16);
    acc.y += __shfl_xor_sync(FULLM, acc.y, 16);
    acc.z += __shfl_xor_sync(FULLM, acc.z, 16);
    acc.w += __shfl_xor_sync(FULLM, acc.w, 16);
    float4 v4 = make_float4(acc.x*inv, acc.y*inv, acc.z*inv, acc.w*inv);
    if (lane < 16)
        *(float4*)(g_xc + (size_t)bn * HIN_ + c16*4) = v4;

    // score dot s0 = xc_row . aw[0:64]
    float4 a4 = __ldg((const float4*)(aw + c16*4));
    float d = v4.x*a4.x + v4.y*a4.y + v4.z*a4.z + v4.w*a4.w;
#pragma unroll
    for (int off = 1; off < 16; off <<= 1) d += __shfl_xor_sync(FULLM, d, off);
    if (lane == 0) g_s0[bn] = d;
}

// ---------------- kernel 3: softmax over nodes + pooled output -------------
__global__ __launch_bounds__(512) void k_final(
    const float* __restrict__ aw, float* __restrict__ out)
{
    int b = blockIdx.x, t = threadIdx.x;
    int wid = t >> 5, lane = t & 31;
    __shared__ __align__(16) float sc[512];
    __shared__ __align__(16) float red4[32][HIN_];
    __shared__ float wred[16];
    __shared__ float sh_m, sh_inv, sh_rdot;

    if (wid == 0) {
        const float* xr = g_xc + (size_t)b * N_ * HIN_;
        float r = xr[lane] * __ldg(aw + HIN_ + lane)
                + xr[lane + 32] * __ldg(aw + HIN_ + lane + 32);
#pragma unroll
        for (int off = 16; off; off >>= 1) r += __shfl_xor_sync(FULLM, r, off);
        if (lane == 0) sh_rdot = r;
    }
    __syncthreads();
    float rdot = sh_rdot;

    float s = -3e38f;
    if (t < N_) {
        s = g_s0[b * N_ + t];
        if (t < NV_) s += rdot;
        if (s == 0.f) s = NEG_INF_;
        sc[t] = s;
    }
    float m = s;
#pragma unroll
    for (int off = 16; off; off >>= 1) m = fmaxf(m, __shfl_xor_sync(FULLM, m, off));
    if (lane == 0) wred[wid] = m;
    __syncthreads();
    if (t < 32) {
        float mm = (t < 16) ? wred[t] : -3e38f;
#pragma unroll
        for (int off = 8; off; off >>= 1) mm = fmaxf(mm, __shfl_xor_sync(FULLM, mm, off));
        if (t == 0) sh_m = mm;
    }
    __syncthreads();
    m = sh_m;

    float p = (t < N_) ? __expf(sc[t] - m) : 0.f;
    if (t < N_) sc[t] = p;
    float ls = p;
#pragma unroll
    for (int off = 16; off; off >>= 1) ls += __shfl_xor_sync(FULLM, ls, off);
    if (lane == 0) wred[wid] = ls;
    __syncthreads();
    if (t < 32) {
        float ss = (t < 16) ? wred[t] : 0.f;
#pragma unroll
        for (int off = 8; off; off >>= 1) ss += __shfl_xor_sync(FULLM, ss, off);
        if (t == 0) sh_inv = 1.f / ss;
    }
    __syncthreads();
    float inv = sh_inv;

    if (t < N_) out[B_ * HIN_ + b * N_ + t] = p * inv;

    int g = t >> 4, o4 = (t & 15) << 2;
    const float* base = g_xc + (size_t)b * N_ * HIN_ + o4;
    float4 acc = make_float4(0.f, 0.f, 0.f, 0.f);
    for (int n = g; n < N_; n += 32) {
        float w = sc[n];
        float4 hv = *(const float4*)(base + (size_t)n * HIN_);
        acc.x += w*hv.x; acc.y += w*hv.y; acc.z += w*hv.z; acc.w += w*hv.w;
    }
    *(float4*)&red4[g][o4] = acc;
    __syncthreads();
    if (t < HIN_) {
        float tot = 0.f;
#pragma unroll
        for (int k = 0; k < 32; k++) tot += red4[k][t];
        out[b * HIN_ + t] = tot * inv;
    }
}

// ---------------------------------------------------------------------------
extern "C" void kernel_launch(void* const* d_in, const int* in_sizes, int n_in,
                              void* d_out, int out_size)
{
    const float* x       = (const float*)d_in[0];
    const float* A       = (const float*)d_in[1];
    const float* w1      = (const float*)d_in[4];
    const float* a_src1  = (const float*)d_in[5];
    const float* a_dst1  = (const float*)d_in[6];
    const float* w2      = (const float*)d_in[7];
    const float* a_src2  = (const float*)d_in[8];
    const float* a_dst2  = (const float*)d_in[9];
    const float* attn_w  = (const float*)d_in[10];
    float* out = (float*)d_out;

    k_proj1     <<<B_ * N_ / 32, 256>>>(x, w1, a_src1, a_dst1);
    k_attn1proj2<<<B_ * N_, 256>>>(A, w2, a_src2, a_dst2);
    k_attn2     <<<B_ * N_ / 8, 256>>>(attn_w);
    k_final     <<<B_, 512>>>(attn_w, out);
}

// round 14
// speedup vs baseline: 1.5904x; 1.5904x over previous
#include <cuda_runtime.h>
#include <cuda_bf16.h>
#include <cuda_fp16.h>

#define B_    32
#define N_    500
#define NV_   400
#define HIN_  64
#define HID_  16
#define NH_   8
#define HC_   128   // NH*HID
#define CAP_  96
#define STR2_ 34    // padded stride for 32-row transposed x tile
#define NEG_INF_ -1e20f
#define FULLM 0xffffffffu

// ---------------- scratch (device globals; 16B-aligned) --------------------
__device__ __align__(16) __half g_h1h [B_*N_*HC_];   // layer-1 proj, fp16 [bn][128]
__device__ float g_es1  [B_*NH_*N_];
__device__ float g_ed1  [B_*NH_*N_];
__device__ __align__(16) __half g_h2h [B_*N_*HIN_];  // fp16 [bn][64]
__device__ float g_es2  [B_*N_];
__device__ float g_ed2  [B_*N_];
__device__ __align__(16) float g_xc   [B_*N_*HIN_];  // fp32 [bn][64]
__device__ float g_s0   [B_*N_];                     // xc . attn_w[0:64]
__device__ unsigned short g_nidx[B_*N_*CAP_];
__device__ int            g_nnz [B_*N_];

// ---------------- fused kernel 0: compaction (blocks 0..1999) --------------
//                  + layer-1 projection (blocks 2000..2499, 32-row tiles) ---
__device__ __forceinline__ void compact_body(int bid, const float* __restrict__ A)
{
    int w = threadIdx.x >> 5, lane = threadIdx.x & 31;
    int bn = bid * 8 + w;
    const float4* row = (const float4*)(A + (size_t)bn * N_);   // 125 float4
    unsigned short* out = g_nidx + (size_t)bn * CAP_;

    float4 v[4];
#pragma unroll
    for (int r = 0; r < 4; r++) {
        int q = r * 32 + lane;
        v[r] = (q < 125) ? __ldg(row + q) : make_float4(0.f, 0.f, 0.f, 0.f);
    }

    int cnt = 0;
#pragma unroll
    for (int r = 0; r < 4; r++) {
        int q = r * 32 + lane;
        unsigned m4 = (v[r].x > 0.f) | ((v[r].y > 0.f) << 1)
                    | ((v[r].z > 0.f) << 2) | ((v[r].w > 0.f) << 3);
        if (q >= 125) m4 = 0;
        int c4 = __popc(m4);
        int inc = c4;
#pragma unroll
        for (int off = 1; off < 32; off <<= 1) {
            int nb = __shfl_up_sync(FULLM, inc, off);
            if (lane >= off) inc += nb;
        }
        int excl = inc - c4;
        int basej = q << 2;
#pragma unroll
        for (int e = 0; e < 4; e++)
            if (m4 & (1u << e)) {
                int pos = cnt + excl + __popc(m4 & ((1u << e) - 1u));
                if (pos < CAP_) out[pos] = (unsigned short)(basej + e);
            }
        cnt += __shfl_sync(FULLM, inc, 31);
    }
    if (lane == 0) g_nnz[bn] = cnt < CAP_ ? cnt : CAP_;
}

// 32-row x 128-col tile; thread = 2x8. ~40 regs -> high occupancy for the
// co-resident compaction blocks.
__device__ __forceinline__ void proj1_body(int bid,
    const float* __restrict__ x, const float* __restrict__ w1,
    const float* __restrict__ a_src1, const float* __restrict__ a_dst1,
    float* xt)
{
    int t = threadIdx.x;
    int gbase = bid * 32;

    for (int i = t; i < 512; i += 256) {       // 32 rows x 16 float4, transposed
        int row = i >> 4, fg = (i & 15) << 2;
        float4 v = *(const float4*)(x + (size_t)(gbase + row) * HIN_ + fg);
        xt[(fg+0)*STR2_ + row] = v.x; xt[(fg+1)*STR2_ + row] = v.y;
        xt[(fg+2)*STR2_ + row] = v.z; xt[(fg+3)*STR2_ + row] = v.w;
    }
    __syncthreads();

    int rt = t >> 4, ct = t & 15;              // rows rt*2.., cols ct*8..
    int h = ct >> 1, obase = (ct & 1) << 3;
    const float* wb = w1 + (h << 10) + obase;  // w1[h][f][o], stride 16 per f

    float acc[2][8];
#pragma unroll
    for (int a = 0; a < 2; a++)
#pragma unroll
        for (int c = 0; c < 8; c++) acc[a][c] = 0.f;

#pragma unroll 4
    for (int f = 0; f < HIN_; f++) {
        float2 xv = *(float2*)&xt[f*STR2_ + rt*2];
        float4 w0 = __ldg((const float4*)(wb + (f << 4)));
        float4 w1v= __ldg((const float4*)(wb + (f << 4) + 4));
        float wr[8] = {w0.x,w0.y,w0.z,w0.w,w1v.x,w1v.y,w1v.z,w1v.w};
#pragma unroll
        for (int c = 0; c < 8; c++) {
            acc[0][c] += xv.x * wr[c];
            acc[1][c] += xv.y * wr[c];
        }
    }

    float as[8], ad[8];
#pragma unroll
    for (int c = 0; c < 8; c++) {
        as[c] = __ldg(a_src1 + h*HID_ + obase + c);
        ad[c] = __ldg(a_dst1 + h*HID_ + obase + c);
    }
#pragma unroll
    for (int rr = 0; rr < 2; rr++) {
        int gr = gbase + rt*2 + rr;
        int b = gr / N_, n = gr % N_;
        __align__(16) __half2 hp[4];
        hp[0] = __floats2half2_rn(acc[rr][0], acc[rr][1]);
        hp[1] = __floats2half2_rn(acc[rr][2], acc[rr][3]);
        hp[2] = __floats2half2_rn(acc[rr][4], acc[rr][5]);
        hp[3] = __floats2half2_rn(acc[rr][6], acc[rr][7]);
        *(uint4*)(g_h1h + (size_t)gr * HC_ + ct*8) = *(uint4*)hp;
        float ps = 0.f, pd = 0.f;
#pragma unroll
        for (int c = 0; c < 8; c++) { ps += acc[rr][c]*as[c]; pd += acc[rr][c]*ad[c]; }
        ps += __shfl_xor_sync(FULLM, ps, 1);
        pd += __shfl_xor_sync(FULLM, pd, 1);
        if ((ct & 1) == 0) {
            g_es1[(b*NH_ + h) * N_ + n] = ps;
            g_ed1[(b*NH_ + h) * N_ + n] = pd;
        }
    }
}

__global__ __launch_bounds__(256) void k_fused0(
    const float* __restrict__ A, const float* __restrict__ x,
    const float* __restrict__ w1,
    const float* __restrict__ a_src1, const float* __restrict__ a_dst1)
{
    __shared__ __align__(16) float xt[HIN_ * STR2_];
    if (blockIdx.x < 2000) compact_body(blockIdx.x, A);
    else                   proj1_body(blockIdx.x - 2000, x, w1, a_src1, a_dst1, xt);
}

// ---------------- kernel 1: layer-1 attention + ELU + layer-2 proj ---------
__global__ __launch_bounds__(256) void k_attn1proj2(
    const float* __restrict__ w2,
    const float* __restrict__ a_src2, const float* __restrict__ a_dst2)
{
    int bn = blockIdx.x;
    int b = bn / N_, i = bn % N_;
    __shared__ __align__(16) float red[8][HC_];
    __shared__ __align__(16) float sp[NH_][CAP_];
    __shared__ __align__(16) float hcat[HC_];
    __shared__ __align__(16) float h2s[HIN_];
    __shared__ int   snj[CAP_];
    __shared__ float sinv[NH_];
    int t = threadIdx.x, h = t >> 5, lane = t & 31;
    int nnz = g_nnz[bn];

    const unsigned short* nidx = g_nidx + (size_t)bn * CAP_;
    if (t < nnz) snj[t] = nidx[t];
    __syncthreads();

    // phase 1: per-head unnormalized softmax weights (|e| small; no max)
    float es = g_es1[(b*NH_ + h) * N_ + i];
    const float* ed = g_ed1 + (b*NH_ + h) * N_;
    float sum = 0.f;
    for (int k = lane; k < nnz; k += 32) {
        float e = es + ed[snj[k]];
        e = (e > 0.f) ? e : 0.2f * e;
        float p = __expf(e);
        sp[h][k] = p;
        sum += p;
    }
#pragma unroll
    for (int off = 16; off; off >>= 1) sum += __shfl_xor_sync(FULLM, sum, off);
    if (lane == 0) sinv[h] = 1.f / sum;
    __syncthreads();

    // phase 2: slice = warp, q4 = 4-channel group; fp16 uint2 gathers (8 B)
    int slice = t >> 5, q4 = (t & 31) << 2, hh = q4 >> 4;
    const __half* base = g_h1h + (size_t)b * N_ * HC_ + q4;
    float4 acc = make_float4(0.f, 0.f, 0.f, 0.f);
    for (int k = slice; k < nnz; k += 8) {
        float w = sp[hh][k];
        uint2 u = *(const uint2*)(base + (size_t)snj[k] * HC_);
        float2 f0 = __half22float2(*(__half2*)&u.x);
        float2 f1 = __half22float2(*(__half2*)&u.y);
        acc.x += w*f0.x; acc.y += w*f0.y; acc.z += w*f1.x; acc.w += w*f1.y;
    }
    *(float4*)&red[slice][q4] = acc;
    __syncthreads();

    if (t < HC_) {
        float s = 0.f;
#pragma unroll
        for (int s8 = 0; s8 < 8; s8++) s += red[s8][t];
        float v = s * sinv[t >> 4];
        v = (v > 0.f) ? v : (__expf(v) - 1.f);   // ELU
        hcat[t] = v;
    }
    __syncthreads();

    // phase 3: matvec h2[o] = sum_f hcat[f]*w2[f][o]; 4 f-groups x 64 o
    {
        int o = t & 63, g = t >> 6;
        const float* wv = w2 + (g << 5) * HIN_ + o;
        float a2 = 0.f;
#pragma unroll 8
        for (int f = 0; f < 32; f++) a2 += hcat[(g << 5) + f] * wv[f * HIN_];
        red[g][o] = a2;
    }
    __syncthreads();
    if (t < HIN_) {
        float hv = red[0][t] + red[1][t] + red[2][t] + red[3][t];
        h2s[t] = hv;
        g_h2h[(size_t)bn * HIN_ + t] = __float2half_rn(hv);
    }
    __syncthreads();
    if (t < 32) {
        float v0 = h2s[t], v1 = h2s[t + 32];
        float ps = v0 * __ldg(a_src2 + t) + v1 * __ldg(a_src2 + t + 32);
        float pd = v0 * __ldg(a_dst2 + t) + v1 * __ldg(a_dst2 + t + 32);
#pragma unroll
        for (int off = 16; off; off >>= 1) {
            ps += __shfl_xor_sync(FULLM, ps, off);
            pd += __shfl_xor_sync(FULLM, pd, off);
        }
        if (t == 0) { g_es2[bn] = ps; g_ed2[bn] = pd; }
    }
}

// ---------------- kernel 2: layer-2 attention + score dot ------------------
// 2000 blocks x 256 threads; warp per row. No smem/barriers. fp16 gathers.
__global__ __launch_bounds__(256) void k_attn2(const float* __restrict__ aw)
{
    int wid = threadIdx.x >> 5, lane = threadIdx.x & 31;
    int bn = blockIdx.x * 8 + wid;
    int b = bn / N_, i = bn % N_;

    if (i >= NV_) {                          // padded node: zero row + score
        if (lane < 16)
            *(float4*)(g_xc + (size_t)bn * HIN_ + lane*4) =
                make_float4(0.f, 0.f, 0.f, 0.f);
        if (lane == 0) g_s0[bn] = 0.f;
        return;
    }

    int nnz = g_nnz[bn];
    const unsigned short* nidx = g_nidx + (size_t)bn * CAP_;
    int idx0 = (lane      < nnz) ? nidx[lane]      : 0;
    int idx1 = (lane + 32 < nnz) ? nidx[lane + 32] : 0;
    int idx2 = (lane + 64 < nnz) ? nidx[lane + 64] : 0;

    float es = g_es2[bn];
    const float* ed = g_ed2 + b * N_;
    float p0 = 0.f, p1 = 0.f, p2 = 0.f;
    if (lane < nnz)      { float e = es + ed[idx0]; e = (e>0.f)?e:0.2f*e; p0 = __expf(e); }
    if (lane + 32 < nnz) { float e = es + ed[idx1]; e = (e>0.f)?e:0.2f*e; p1 = __expf(e); }
    if (lane + 64 < nnz) { float e = es + ed[idx2]; e = (e>0.f)?e:0.2f*e; p2 = __expf(e); }
    float sum = p0 + p1 + p2;
#pragma unroll
    for (int off = 16; off; off >>= 1) sum += __shfl_xor_sync(FULLM, sum, off);
    float inv = 1.f / sum;

    int slice = lane >> 4, c16 = lane & 15;
    const __half* base = g_h2h + (size_t)b * N_ * HIN_ + c16 * 4;
    float4 acc = make_float4(0.f, 0.f, 0.f, 0.f);
    int mcnt = (nnz + 1) >> 1;
#pragma unroll 4
    for (int m = 0; m < mcnt; m++) {
        int k = slice + (m << 1);
        int ri = (m >> 4);                    // (2m+slice)>>5 — warp-uniform
        float ps = (ri == 0) ? p0 : ((ri == 1) ? p1 : p2);
        int   is = (ri == 0) ? idx0 : ((ri == 1) ? idx1 : idx2);
        float pv = __shfl_sync(FULLM, ps, k & 31);
        int   jj = __shfl_sync(FULLM, is, k & 31);
        if (k < nnz) {
            uint2 u = *(const uint2*)(base + (size_t)jj * HIN_);
            float2 f0 = __half22float2(*(__half2*)&u.x);
            float2 f1 = __half22float2(*(__half2*)&u.y);
            acc.x += pv*f0.x; acc.y += pv*f0.y; acc.z += pv*f1.x; acc.w += pv*f1.y;
        }
    }
    acc.x += __shfl_xor_sync(FULLM, acc.x, 16);
    acc.y += __shfl_xor_sync(FULLM, acc.y, 16);
    acc.z += __shfl_xor_sync(FULLM, acc.z, 16);
    acc.w += __shfl_xor_sync(FULLM, acc.w, 16);
    float4 v4 = make_float4(acc.x*inv, acc.y*inv, acc.z*inv, acc.w*inv);
    if (lane < 16)
        *(float4*)(g_xc + (size_t)bn * HIN_ + c16*4) = v4;

    float4 a4 = __ldg((const float4*)(aw + c16*4));
    float d = v4.x*a4.x + v4.y*a4.y + v4.z*a4.z + v4.w*a4.w;
#pragma unroll
    for (int off = 1; off < 16; off <<= 1) d += __shfl_xor_sync(FULLM, d, off);
    if (lane == 0) g_s0[bn] = d;
}

// ---------------- kernel 3: softmax over nodes + pooled output -------------
__global__ __launch_bounds__(512) void k_final(
    const float* __restrict__ aw, float* __restrict__ out)
{
    int b = blockIdx.x, t = threadIdx.x;
    int wid = t >> 5, lane = t & 31;
    __shared__ __align__(16) float sc[512];
    __shared__ __align__(16) float red4[32][HIN_];
    __shared__ float wred[16];
    __shared__ float sh_m, sh_inv, sh_rdot;

    if (wid == 0) {
        const float* xr = g_xc + (size_t)b * N_ * HIN_;
        float r = xr[lane] * __ldg(aw + HIN_ + lane)
                + xr[lane + 32] * __ldg(aw + HIN_ + lane + 32);
#pragma unroll
        for (int off = 16; off; off >>= 1) r += __shfl_xor_sync(FULLM, r, off);
        if (lane == 0) sh_rdot = r;
    }
    __syncthreads();
    float rdot = sh_rdot;

    float s = -3e38f;
    if (t < N_) {
        s = g_s0[b * N_ + t];
        if (t < NV_) s += rdot;
        if (s == 0.f) s = NEG_INF_;
        sc[t] = s;
    }
    float m = s;
#pragma unroll
    for (int off = 16; off; off >>= 1) m = fmaxf(m, __shfl_xor_sync(FULLM, m, off));
    if (lane == 0) wred[wid] = m;
    __syncthreads();
    if (t < 32) {
        float mm = (t < 16) ? wred[t] : -3e38f;
#pragma unroll
        for (int off = 8; off; off >>= 1) mm = fmaxf(mm, __shfl_xor_sync(FULLM, mm, off));
        if (t == 0) sh_m = mm;
    }
    __syncthreads();
    m = sh_m;

    float p = (t < N_) ? __expf(sc[t] - m) : 0.f;
    if (t < N_) sc[t] = p;
    float ls = p;
#pragma unroll
    for (int off = 16; off; off >>= 1) ls += __shfl_xor_sync(FULLM, ls, off);
    if (lane == 0) wred[wid] = ls;
    __syncthreads();
    if (t < 32) {
        float ss = (t < 16) ? wred[t] : 0.f;
#pragma unroll
        for (int off = 8; off; off >>= 1) ss += __shfl_xor_sync(FULLM, ss, off);
        if (t == 0) sh_inv = 1.f / ss;
    }
    __syncthreads();
    float inv = sh_inv;

    if (t < N_) out[B_ * HIN_ + b * N_ + t] = p * inv;

    int g = t >> 4, o4 = (t & 15) << 2;
    const float* base = g_xc + (size_t)b * N_ * HIN_ + o4;
    float4 acc = make_float4(0.f, 0.f, 0.f, 0.f);
    for (int n = g; n < N_; n += 32) {
        float w = sc[n];
        float4 hv = *(const float4*)(base + (size_t)n * HIN_);
        acc.x += w*hv.x; acc.y += w*hv.y; acc.z += w*hv.z; acc.w += w*hv.w;
    }
    *(float4*)&red4[g][o4] = acc;
    __syncthreads();
    if (t < HIN_) {
        float tot = 0.f;
#pragma unroll
        for (int k = 0; k < 32; k++) tot += red4[k][t];
        out[b * HIN_ + t] = tot * inv;
    }
}

// ---------------------------------------------------------------------------
extern "C" void kernel_launch(void* const* d_in, const int* in_sizes, int n_in,
                              void* d_out, int out_size)
{
    const float* x       = (const float*)d_in[0];
    const float* A       = (const float*)d_in[1];
    const float* w1      = (const float*)d_in[4];
    const float* a_src1  = (const float*)d_in[5];
    const float* a_dst1  = (const float*)d_in[6];
    const float* w2      = (const float*)d_in[7];
    const float* a_src2  = (const float*)d_in[8];
    const float* a_dst2  = (const float*)d_in[9];
    const float* attn_w  = (const float*)d_in[10];
    float* out = (float*)d_out;

    k_fused0    <<<2500, 256>>>(A, x, w1, a_src1, a_dst1);
    k_attn1proj2<<<B_ * N_, 256>>>(w2, a_src2, a_dst2);
    k_attn2     <<<B_ * N_ / 8, 256>>>(attn_w);
    k_final     <<<B_, 512>>>(attn_w, out);
}

// round 15
// speedup vs baseline: 1.6148x; 1.0154x over previous
#include <cuda_runtime.h>
#include <cuda_bf16.h>
#include <cuda_fp16.h>

#define B_    32
#define N_    500
#define NV_   400
#define HIN_  64
#define HID_  16
#define NH_   8
#define HC_   128   // NH*HID
#define CAP_  96
#define STR_  68
#define NEG_INF_ -1e20f
#define FULLM 0xffffffffu

// ---------------- scratch (device globals; 16B-aligned) --------------------
__device__ __align__(16) __half g_h1h [B_*N_*HC_];   // layer-1 proj, fp16 [bn][128]
__device__ __align__(16) float g_es1  [B_*N_*NH_];   // TRANSPOSED: [bn][h]
__device__ __align__(16) float g_ed1  [B_*N_*NH_];   // TRANSPOSED: [bn][h]
__device__ __align__(16) __half g_h2h [B_*N_*HIN_];  // fp16 [bn][64]
__device__ float g_es2  [B_*N_];
__device__ float g_ed2  [B_*N_];
__device__ __align__(16) float g_xc   [B_*N_*HIN_];  // fp32 [bn][64]
__device__ float g_s0   [B_*N_];                     // xc . attn_w[0:64]
__device__ unsigned short g_nidx[B_*N_*CAP_];
__device__ int            g_nnz [B_*N_];

// ---------------- fused kernel 0: compaction (blocks 0..1999) --------------
//                  + layer-1 tiled projection (blocks 2000..2249) -----------
__device__ __forceinline__ void compact_body(int bid, const float* __restrict__ A)
{
    int w = threadIdx.x >> 5, lane = threadIdx.x & 31;
    int bn = bid * 8 + w;
    const float4* row = (const float4*)(A + (size_t)bn * N_);   // 125 float4
    unsigned short* out = g_nidx + (size_t)bn * CAP_;

    float4 v[4];
#pragma unroll
    for (int r = 0; r < 4; r++) {
        int q = r * 32 + lane;
        v[r] = (q < 125) ? __ldg(row + q) : make_float4(0.f, 0.f, 0.f, 0.f);
    }

    int cnt = 0;
#pragma unroll
    for (int r = 0; r < 4; r++) {
        int q = r * 32 + lane;
        unsigned m4 = (v[r].x > 0.f) | ((v[r].y > 0.f) << 1)
                    | ((v[r].z > 0.f) << 2) | ((v[r].w > 0.f) << 3);
        if (q >= 125) m4 = 0;
        int c4 = __popc(m4);
        int inc = c4;
#pragma unroll
        for (int off = 1; off < 32; off <<= 1) {
            int nb = __shfl_up_sync(FULLM, inc, off);
            if (lane >= off) inc += nb;
        }
        int excl = inc - c4;
        int basej = q << 2;
#pragma unroll
        for (int e = 0; e < 4; e++)
            if (m4 & (1u << e)) {
                int pos = cnt + excl + __popc(m4 & ((1u << e) - 1u));
                if (pos < CAP_) out[pos] = (unsigned short)(basej + e);
            }
        cnt += __shfl_sync(FULLM, inc, 31);
    }
    if (lane == 0) g_nnz[bn] = cnt < CAP_ ? cnt : CAP_;
}

__device__ __forceinline__ void proj1_body(int bid,
    const float* __restrict__ x, const float* __restrict__ w1,
    const float* __restrict__ a_src1, const float* __restrict__ a_dst1,
    float* xt)
{
    int t = threadIdx.x;
    int gbase = bid * 64;

    for (int i = t; i < 1024; i += 256) {      // 64 rows x 16 float4, transposed
        int row = i >> 4, fg = (i & 15) << 2;
        float4 v = *(const float4*)(x + (size_t)(gbase + row) * HIN_ + fg);
        xt[(fg+0)*STR_ + row] = v.x; xt[(fg+1)*STR_ + row] = v.y;
        xt[(fg+2)*STR_ + row] = v.z; xt[(fg+3)*STR_ + row] = v.w;
    }
    __syncthreads();

    int rt = t >> 4, ct = t & 15;              // rows rt*4.., cols ct*8..
    int h = ct >> 1, obase = (ct & 1) << 3;
    const float* wb = w1 + (h << 10) + obase;  // w1[h][f][o], stride 16 per f

    float acc[4][8];
#pragma unroll
    for (int a = 0; a < 4; a++)
#pragma unroll
        for (int c = 0; c < 8; c++) acc[a][c] = 0.f;

#pragma unroll 4
    for (int f = 0; f < HIN_; f++) {
        float4 xv = *(float4*)&xt[f*STR_ + rt*4];
        float4 w0 = __ldg((const float4*)(wb + (f << 4)));
        float4 w1v= __ldg((const float4*)(wb + (f << 4) + 4));
        float xr[4] = {xv.x, xv.y, xv.z, xv.w};
        float wr[8] = {w0.x,w0.y,w0.z,w0.w,w1v.x,w1v.y,w1v.z,w1v.w};
#pragma unroll
        for (int a = 0; a < 4; a++)
#pragma unroll
            for (int c = 0; c < 8; c++) acc[a][c] += xr[a] * wr[c];
    }

    float as[8], ad[8];
#pragma unroll
    for (int c = 0; c < 8; c++) {
        as[c] = __ldg(a_src1 + h*HID_ + obase + c);
        ad[c] = __ldg(a_dst1 + h*HID_ + obase + c);
    }
#pragma unroll
    for (int rr = 0; rr < 4; rr++) {
        int gr = gbase + rt*4 + rr;
        __align__(16) __half2 hp[4];
        hp[0] = __floats2half2_rn(acc[rr][0], acc[rr][1]);
        hp[1] = __floats2half2_rn(acc[rr][2], acc[rr][3]);
        hp[2] = __floats2half2_rn(acc[rr][4], acc[rr][5]);
        hp[3] = __floats2half2_rn(acc[rr][6], acc[rr][7]);
        *(uint4*)(g_h1h + (size_t)gr * HC_ + ct*8) = *(uint4*)hp;
        float ps = 0.f, pd = 0.f;
#pragma unroll
        for (int c = 0; c < 8; c++) { ps += acc[rr][c]*as[c]; pd += acc[rr][c]*ad[c]; }
        ps += __shfl_xor_sync(FULLM, ps, 1);
        pd += __shfl_xor_sync(FULLM, pd, 1);
        if ((ct & 1) == 0) {                   // 8 writers -> 32B contiguous
            g_es1[gr * NH_ + h] = ps;
            g_ed1[gr * NH_ + h] = pd;
        }
    }
}

__global__ __launch_bounds__(256) void k_fused0(
    const float* __restrict__ A, const float* __restrict__ x,
    const float* __restrict__ w1,
    const float* __restrict__ a_src1, const float* __restrict__ a_dst1)
{
    __shared__ __align__(16) float xt[HIN_ * STR_];
    if (blockIdx.x < 2000) compact_body(blockIdx.x, A);
    else                   proj1_body(blockIdx.x - 2000, x, w1, a_src1, a_dst1, xt);
}

// ---------------- kernel 1: layer-1 attention + ELU + layer-2 proj ---------
__global__ __launch_bounds__(256) void k_attn1proj2(
    const float* __restrict__ w2,
    const float* __restrict__ a_src2, const float* __restrict__ a_dst2)
{
    int bn = blockIdx.x;
    int b = bn / N_;
    __shared__ __align__(16) float red[8][HC_];
    __shared__ __align__(16) float sp[NH_][CAP_];
    __shared__ __align__(16) float hcat[HC_];
    __shared__ __align__(16) float h2s[HIN_];
    __shared__ int   snj[CAP_];
    __shared__ float sinv[NH_];
    int t = threadIdx.x, h = t >> 5, lane = t & 31;
    int nnz = g_nnz[bn];

    const unsigned short* nidx = g_nidx + (size_t)bn * CAP_;
    if (t < nnz) snj[t] = nidx[t];
    __syncthreads();

    // phase 1: per-head softmax weights. ed1 is [node][head]: all 8 warps
    // hit the SAME 32B sector per neighbor -> 8x L1 reuse.
    float es = g_es1[bn * NH_ + h];
    const float* edt = g_ed1 + (size_t)b * N_ * NH_;
    float sum = 0.f;
    for (int k = lane; k < nnz; k += 32) {
        float e = es + edt[snj[k] * NH_ + h];
        e = (e > 0.f) ? e : 0.2f * e;
        float p = __expf(e);
        sp[h][k] = p;
        sum += p;
    }
#pragma unroll
    for (int off = 16; off; off >>= 1) sum += __shfl_xor_sync(FULLM, sum, off);
    if (lane == 0) sinv[h] = 1.f / sum;
    __syncthreads();

    // phase 2: slice = warp, q4 = 4-channel group; fp16 uint2 gathers (8 B)
    int slice = t >> 5, q4 = (t & 31) << 2, hh = q4 >> 4;
    const __half* base = g_h1h + (size_t)b * N_ * HC_ + q4;
    float4 acc = make_float4(0.f, 0.f, 0.f, 0.f);
    for (int k = slice; k < nnz; k += 8) {
        float w = sp[hh][k];
        uint2 u = *(const uint2*)(base + (size_t)snj[k] * HC_);
        float2 f0 = __half22float2(*(__half2*)&u.x);
        float2 f1 = __half22float2(*(__half2*)&u.y);
        acc.x += w*f0.x; acc.y += w*f0.y; acc.z += w*f1.x; acc.w += w*f1.y;
    }
    *(float4*)&red[slice][q4] = acc;
    __syncthreads();

    if (t < HC_) {
        float s = 0.f;
#pragma unroll
        for (int s8 = 0; s8 < 8; s8++) s += red[s8][t];
        float v = s * sinv[t >> 4];
        v = (v > 0.f) ? v : (__expf(v) - 1.f);   // ELU
        hcat[t] = v;
    }
    __syncthreads();

    // phase 3: matvec h2[o] = sum_f hcat[f]*w2[f][o]; 4 f-groups x 64 o
    {
        int o = t & 63, g = t >> 6;
        const float* wv = w2 + (g << 5) * HIN_ + o;
        float a2 = 0.f;
#pragma unroll 8
        for (int f = 0; f < 32; f++) a2 += hcat[(g << 5) + f] * wv[f * HIN_];
        red[g][o] = a2;
    }
    __syncthreads();
    if (t < HIN_) {
        float hv = red[0][t] + red[1][t] + red[2][t] + red[3][t];
        h2s[t] = hv;
        g_h2h[(size_t)bn * HIN_ + t] = __float2half_rn(hv);
    }
    __syncthreads();
    if (t < 32) {
        float v0 = h2s[t], v1 = h2s[t + 32];
        float ps = v0 * __ldg(a_src2 + t) + v1 * __ldg(a_src2 + t + 32);
        float pd = v0 * __ldg(a_dst2 + t) + v1 * __ldg(a_dst2 + t + 32);
#pragma unroll
        for (int off = 16; off; off >>= 1) {
            ps += __shfl_xor_sync(FULLM, ps, off);
            pd += __shfl_xor_sync(FULLM, pd, off);
        }
        if (t == 0) { g_es2[bn] = ps; g_ed2[bn] = pd; }
    }
}

// ---------------- kernel 2: layer-2 attention + score dot ------------------
// 2000 blocks x 256 threads; warp per row. No smem/barriers. fp16 gathers.
__global__ __launch_bounds__(256) void k_attn2(const float* __restrict__ aw)
{
    int wid = threadIdx.x >> 5, lane = threadIdx.x & 31;
    int bn = blockIdx.x * 8 + wid;
    int b = bn / N_, i = bn % N_;

    if (i >= NV_) {                          // padded node: zero row + score
        if (lane < 16)
            *(float4*)(g_xc + (size_t)bn * HIN_ + lane*4) =
                make_float4(0.f, 0.f, 0.f, 0.f);
        if (lane == 0) g_s0[bn] = 0.f;
        return;
    }

    int nnz = g_nnz[bn];
    const unsigned short* nidx = g_nidx + (size_t)bn * CAP_;
    int idx0 = (lane      < nnz) ? nidx[lane]      : 0;
    int idx1 = (lane + 32 < nnz) ? nidx[lane + 32] : 0;
    int idx2 = (lane + 64 < nnz) ? nidx[lane + 64] : 0;

    float es = g_es2[bn];
    const float* ed = g_ed2 + b * N_;
    float p0 = 0.f, p1 = 0.f, p2 = 0.f;
    if (lane < nnz)      { float e = es + ed[idx0]; e = (e>0.f)?e:0.2f*e; p0 = __expf(e); }
    if (lane + 32 < nnz) { float e = es + ed[idx1]; e = (e>0.f)?e:0.2f*e; p1 = __expf(e); }
    if (lane + 64 < nnz) { float e = es + ed[idx2]; e = (e>0.f)?e:0.2f*e; p2 = __expf(e); }
    float sum = p0 + p1 + p2;
#pragma unroll
    for (int off = 16; off; off >>= 1) sum += __shfl_xor_sync(FULLM, sum, off);
    float inv = 1.f / sum;

    int slice = lane >> 4, c16 = lane & 15;
    const __half* base = g_h2h + (size_t)b * N_ * HIN_ + c16 * 4;
    float4 acc = make_float4(0.f, 0.f, 0.f, 0.f);
    int mcnt = (nnz + 1) >> 1;
#pragma unroll 4
    for (int m = 0; m < mcnt; m++) {
        int k = slice + (m << 1);
        int ri = (m >> 4);                    // (2m+slice)>>5 — warp-uniform
        float ps = (ri == 0) ? p0 : ((ri == 1) ? p1 : p2);
        int   is = (ri == 0) ? idx0 : ((ri == 1) ? idx1 : idx2);
        float pv = __shfl_sync(FULLM, ps, k & 31);
        int   jj = __shfl_sync(FULLM, is, k & 31);
        if (k < nnz) {
            uint2 u = *(const uint2*)(base + (size_t)jj * HIN_);
            float2 f0 = __half22float2(*(__half2*)&u.x);
            float2 f1 = __half22float2(*(__half2*)&u.y);
            acc.x += pv*f0.x; acc.y += pv*f0.y; acc.z += pv*f1.x; acc.w += pv*f1.y;
        }
    }
    acc.x += __shfl_xor_sync(FULLM, acc.x, 16);
    acc.y += __shfl_xor_sync(FULLM, acc.y, 16);
    acc.z += __shfl_xor_sync(FULLM, acc.z, 16);
    acc.w += __shfl_xor_sync(FULLM, acc.w, 16);
    float4 v4 = make_float4(acc.x*inv, acc.y*inv, acc.z*inv, acc.w*inv);
    if (lane < 16)
        *(float4*)(g_xc + (size_t)bn * HIN_ + c16*4) = v4;

    float4 a4 = __ldg((const float4*)(aw + c16*4));
    float d = v4.x*a4.x + v4.y*a4.y + v4.z*a4.z + v4.w*a4.w;
#pragma unroll
    for (int off = 1; off < 16; off <<= 1) d += __shfl_xor_sync(FULLM, d, off);
    if (lane == 0) g_s0[bn] = d;
}

// ---------------- kernel 3: softmax over nodes + pooled output -------------
__global__ __launch_bounds__(512) void k_final(
    const float* __restrict__ aw, float* __restrict__ out)
{
    int b = blockIdx.x, t = threadIdx.x;
    int wid = t >> 5, lane = t & 31;
    __shared__ __align__(16) float sc[512];
    __shared__ __align__(16) float red4[32][HIN_];
    __shared__ float wred[16];
    __shared__ float sh_m, sh_inv, sh_rdot;

    if (wid == 0) {
        const float* xr = g_xc + (size_t)b * N_ * HIN_;
        float r = xr[lane] * __ldg(aw + HIN_ + lane)
                + xr[lane + 32] * __ldg(aw + HIN_ + lane + 32);
#pragma unroll
        for (int off = 16; off; off >>= 1) r += __shfl_xor_sync(FULLM, r, off);
        if (lane == 0) sh_rdot = r;
    }
    __syncthreads();
    float rdot = sh_rdot;

    float s = -3e38f;
    if (t < N_) {
        s = g_s0[b * N_ + t];
        if (t < NV_) s += rdot;
        if (s == 0.f) s = NEG_INF_;
        sc[t] = s;
    }
    float m = s;
#pragma unroll
    for (int off = 16; off; off >>= 1) m = fmaxf(m, __shfl_xor_sync(FULLM, m, off));
    if (lane == 0) wred[wid] = m;
    __syncthreads();
    if (t < 32) {
        float mm = (t < 16) ? wred[t] : -3e38f;
#pragma unroll
        for (int off = 8; off; off >>= 1) mm = fmaxf(mm, __shfl_xor_sync(FULLM, mm, off));
        if (t == 0) sh_m = mm;
    }
    __syncthreads();
    m = sh_m;

    float p = (t < N_) ? __expf(sc[t] - m) : 0.f;
    if (t < N_) sc[t] = p;
    float ls = p;
#pragma unroll
    for (int off = 16; off; off >>= 1) ls += __shfl_xor_sync(FULLM, ls, off);
    if (lane == 0) wred[wid] = ls;
    __syncthreads();
    if (t < 32) {
        float ss = (t < 16) ? wred[t] : 0.f;
#pragma unroll
        for (int off = 8; off; off >>= 1) ss += __shfl_xor_sync(FULLM, ss, off);
        if (t == 0) sh_inv = 1.f / ss;
    }
    __syncthreads();
    float inv = sh_inv;

    if (t < N_) out[B_ * HIN_ + b * N_ + t] = p * inv;

    int g = t >> 4, o4 = (t & 15) << 2;
    const float* base = g_xc + (size_t)b * N_ * HIN_ + o4;
    float4 acc = make_float4(0.f, 0.f, 0.f, 0.f);
    for (int n = g; n < N_; n += 32) {
        float w = sc[n];
        float4 hv = *(const float4*)(base + (size_t)n * HIN_);
        acc.x += w*hv.x; acc.y += w*hv.y; acc.z += w*hv.z; acc.w += w*hv.w;
    }
    *(float4*)&red4[g][o4] = acc;
    __syncthreads();
    if (t < HIN_) {
        float tot = 0.f;
#pragma unroll
        for (int k = 0; k < 32; k++) tot += red4[k][t];
        out[b * HIN_ + t] = tot * inv;
    }
}

// ---------------------------------------------------------------------------
extern "C" void kernel_launch(void* const* d_in, const int* in_sizes, int n_in,
                              void* d_out, int out_size)
{
    const float* x       = (const float*)d_in[0];
    const float* A       = (const float*)d_in[1];
    const float* w1      = (const float*)d_in[4];
    const float* a_src1  = (const float*)d_in[5];
    const float* a_dst1  = (const float*)d_in[6];
    const float* w2      = (const float*)d_in[7];
    const float* a_src2  = (const float*)d_in[8];
    const float* a_dst2  = (const float*)d_in[9];
    const float* attn_w  = (const float*)d_in[10];
    float* out = (float*)d_out;

    k_fused0    <<<2250, 256>>>(A, x, w1, a_src1, a_dst1);
    k_attn1proj2<<<B_ * N_, 256>>>(w2, a_src2, a_dst2);
    k_attn2     <<<B_ * N_ / 8, 256>>>(attn_w);
    k_final     <<<B_, 512>>>(attn_w, out);
}

// round 16
// speedup vs baseline: 1.6601x; 1.0281x over previous
#include <cuda_runtime.h>
#include <cuda_bf16.h>
#include <cuda_fp16.h>

#define B_    32
#define N_    500
#define NV_   400
#define HIN_  64
#define HID_  16
#define NH_   8
#define HC_   128   // NH*HID
#define CAP_  96
#define STR_  68
#define NEG_INF_ -1e20f
#define FULLM 0xffffffffu

// ---------------- scratch (device globals; 16B-aligned) --------------------
__device__ __align__(16) __half g_h1h [B_*N_*HC_];   // layer-1 proj, fp16 [bn][128]
__device__ float g_es1  [B_*NH_*N_];
__device__ float g_ed1  [B_*NH_*N_];
__device__ __align__(16) __half g_h2h [B_*N_*HIN_];  // fp16 [bn][64]
__device__ float g_es2  [B_*N_];
__device__ float g_ed2  [B_*N_];
__device__ __align__(16) float g_xc   [B_*N_*HIN_];  // fp32 [bn][64]
__device__ float g_s0   [B_*N_];                     // xc . attn_w[0:64]
__device__ unsigned short g_nidx[B_*N_*CAP_];
__device__ int            g_nnz [B_*N_];

// ---------------- kernel 0a: adjacency compaction (standalone, low-reg) ----
// 2000 blocks x 256 threads; warp per row. High occupancy -> DRAM-BW bound.
__global__ __launch_bounds__(256) void k_compact(const float* __restrict__ A)
{
    int w = threadIdx.x >> 5, lane = threadIdx.x & 31;
    int bn = blockIdx.x * 8 + w;
    const float4* row = (const float4*)(A + (size_t)bn * N_);   // 125 float4
    unsigned short* out = g_nidx + (size_t)bn * CAP_;

    float4 v[4];
#pragma unroll
    for (int r = 0; r < 4; r++) {
        int q = r * 32 + lane;
        v[r] = (q < 125) ? __ldg(row + q) : make_float4(0.f, 0.f, 0.f, 0.f);
    }

    int cnt = 0;
#pragma unroll
    for (int r = 0; r < 4; r++) {
        int q = r * 32 + lane;
        unsigned m4 = (v[r].x > 0.f) | ((v[r].y > 0.f) << 1)
                    | ((v[r].z > 0.f) << 2) | ((v[r].w > 0.f) << 3);
        if (q >= 125) m4 = 0;
        int c4 = __popc(m4);
        int inc = c4;
#pragma unroll
        for (int off = 1; off < 32; off <<= 1) {
            int nb = __shfl_up_sync(FULLM, inc, off);
            if (lane >= off) inc += nb;
        }
        int excl = inc - c4;
        int basej = q << 2;
#pragma unroll
        for (int e = 0; e < 4; e++)
            if (m4 & (1u << e)) {
                int pos = cnt + excl + __popc(m4 & ((1u << e) - 1u));
                if (pos < CAP_) out[pos] = (unsigned short)(basej + e);
            }
        cnt += __shfl_sync(FULLM, inc, 31);
    }
    if (lane == 0) g_nnz[bn] = cnt < CAP_ ? cnt : CAP_;
}

// ---------------- kernel 0b: layer-1 tiled projection (standalone) ---------
// 250 blocks x 256 threads; block = 64 rows x 128 cols; thread = 4x8 tile.
__global__ __launch_bounds__(256) void k_proj1(
    const float* __restrict__ x, const float* __restrict__ w1,
    const float* __restrict__ a_src1, const float* __restrict__ a_dst1)
{
    __shared__ __align__(16) float xt[HIN_ * STR_];
    int t = threadIdx.x;
    int gbase = blockIdx.x * 64;

    for (int i = t; i < 1024; i += 256) {      // 64 rows x 16 float4, transposed
        int row = i >> 4, fg = (i & 15) << 2;
        float4 v = *(const float4*)(x + (size_t)(gbase + row) * HIN_ + fg);
        xt[(fg+0)*STR_ + row] = v.x; xt[(fg+1)*STR_ + row] = v.y;
        xt[(fg+2)*STR_ + row] = v.z; xt[(fg+3)*STR_ + row] = v.w;
    }
    __syncthreads();

    int rt = t >> 4, ct = t & 15;              // rows rt*4.., cols ct*8..
    int h = ct >> 1, obase = (ct & 1) << 3;
    const float* wb = w1 + (h << 10) + obase;  // w1[h][f][o], stride 16 per f

    float acc[4][8];
#pragma unroll
    for (int a = 0; a < 4; a++)
#pragma unroll
        for (int c = 0; c < 8; c++) acc[a][c] = 0.f;

#pragma unroll 4
    for (int f = 0; f < HIN_; f++) {
        float4 xv = *(float4*)&xt[f*STR_ + rt*4];
        float4 w0 = __ldg((const float4*)(wb + (f << 4)));
        float4 w1v= __ldg((const float4*)(wb + (f << 4) + 4));
        float xr[4] = {xv.x, xv.y, xv.z, xv.w};
        float wr[8] = {w0.x,w0.y,w0.z,w0.w,w1v.x,w1v.y,w1v.z,w1v.w};
#pragma unroll
        for (int a = 0; a < 4; a++)
#pragma unroll
            for (int c = 0; c < 8; c++) acc[a][c] += xr[a] * wr[c];
    }

    float as[8], ad[8];
#pragma unroll
    for (int c = 0; c < 8; c++) {
        as[c] = __ldg(a_src1 + h*HID_ + obase + c);
        ad[c] = __ldg(a_dst1 + h*HID_ + obase + c);
    }
#pragma unroll
    for (int rr = 0; rr < 4; rr++) {
        int gr = gbase + rt*4 + rr;
        int b = gr / N_, n = gr % N_;
        __align__(16) __half2 hp[4];
        hp[0] = __floats2half2_rn(acc[rr][0], acc[rr][1]);
        hp[1] = __floats2half2_rn(acc[rr][2], acc[rr][3]);
        hp[2] = __floats2half2_rn(acc[rr][4], acc[rr][5]);
        hp[3] = __floats2half2_rn(acc[rr][6], acc[rr][7]);
        *(uint4*)(g_h1h + (size_t)gr * HC_ + ct*8) = *(uint4*)hp;
        float ps = 0.f, pd = 0.f;
#pragma unroll
        for (int c = 0; c < 8; c++) { ps += acc[rr][c]*as[c]; pd += acc[rr][c]*ad[c]; }
        ps += __shfl_xor_sync(FULLM, ps, 1);
        pd += __shfl_xor_sync(FULLM, pd, 1);
        if ((ct & 1) == 0) {
            g_es1[(b*NH_ + h) * N_ + n] = ps;
            g_ed1[(b*NH_ + h) * N_ + n] = pd;
        }
    }
}

// ---------------- kernel 1: layer-1 attention + ELU + layer-2 proj ---------
__global__ __launch_bounds__(256) void k_attn1proj2(
    const float* __restrict__ w2,
    const float* __restrict__ a_src2, const float* __restrict__ a_dst2)
{
    int bn = blockIdx.x;
    int b = bn / N_, i = bn % N_;
    __shared__ __align__(16) float red[8][HC_];
    __shared__ __align__(16) float sp[NH_][CAP_];
    __shared__ __align__(16) float hcat[HC_];
    __shared__ __align__(16) float h2s[HIN_];
    __shared__ int   snj[CAP_];
    __shared__ float sinv[NH_];
    int t = threadIdx.x, h = t >> 5, lane = t & 31;
    int nnz = g_nnz[bn];

    const unsigned short* nidx = g_nidx + (size_t)bn * CAP_;
    if (t < nnz) snj[t] = nidx[t];
    __syncthreads();

    // phase 1: per-head unnormalized softmax weights (|e| small; no max)
    float es = g_es1[(b*NH_ + h) * N_ + i];
    const float* ed = g_ed1 + (b*NH_ + h) * N_;
    float sum = 0.f;
    for (int k = lane; k < nnz; k += 32) {
        float e = es + ed[snj[k]];
        e = (e > 0.f) ? e : 0.2f * e;
        float p = __expf(e);
        sp[h][k] = p;
        sum += p;
    }
#pragma unroll
    for (int off = 16; off; off >>= 1) sum += __shfl_xor_sync(FULLM, sum, off);
    if (lane == 0) sinv[h] = 1.f / sum;
    __syncthreads();

    // phase 2: slice = warp, q4 = 4-channel group; fp16 uint2 gathers (8 B)
    int slice = t >> 5, q4 = (t & 31) << 2, hh = q4 >> 4;
    const __half* base = g_h1h + (size_t)b * N_ * HC_ + q4;
    float4 acc = make_float4(0.f, 0.f, 0.f, 0.f);
    for (int k = slice; k < nnz; k += 8) {
        float w = sp[hh][k];
        uint2 u = *(const uint2*)(base + (size_t)snj[k] * HC_);
        float2 f0 = __half22float2(*(__half2*)&u.x);
        float2 f1 = __half22float2(*(__half2*)&u.y);
        acc.x += w*f0.x; acc.y += w*f0.y; acc.z += w*f1.x; acc.w += w*f1.y;
    }
    *(float4*)&red[slice][q4] = acc;
    __syncthreads();

    if (t < HC_) {
        float s = 0.f;
#pragma unroll
        for (int s8 = 0; s8 < 8; s8++) s += red[s8][t];
        float v = s * sinv[t >> 4];
        v = (v > 0.f) ? v : (__expf(v) - 1.f);   // ELU
        hcat[t] = v;
    }
    __syncthreads();

    // phase 3: matvec h2[o] = sum_f hcat[f]*w2[f][o]; 4 f-groups x 64 o
    {
        int o = t & 63, g = t >> 6;
        const float* wv = w2 + (g << 5) * HIN_ + o;
        float a2 = 0.f;
#pragma unroll 8
        for (int f = 0; f < 32; f++) a2 += hcat[(g << 5) + f] * wv[f * HIN_];
        red[g][o] = a2;
    }
    __syncthreads();
    if (t < HIN_) {
        float hv = red[0][t] + red[1][t] + red[2][t] + red[3][t];
        h2s[t] = hv;
        g_h2h[(size_t)bn * HIN_ + t] = __float2half_rn(hv);
    }
    __syncthreads();
    if (t < 32) {
        float v0 = h2s[t], v1 = h2s[t + 32];
        float ps = v0 * __ldg(a_src2 + t) + v1 * __ldg(a_src2 + t + 32);
        float pd = v0 * __ldg(a_dst2 + t) + v1 * __ldg(a_dst2 + t + 32);
#pragma unroll
        for (int off = 16; off; off >>= 1) {
            ps += __shfl_xor_sync(FULLM, ps, off);
            pd += __shfl_xor_sync(FULLM, pd, off);
        }
        if (t == 0) { g_es2[bn] = ps; g_ed2[bn] = pd; }
    }
}

// ---------------- kernel 2: layer-2 attention + score dot ------------------
// 2000 blocks x 256 threads; warp per row. No smem/barriers. fp16 gathers.
__global__ __launch_bounds__(256) void k_attn2(const float* __restrict__ aw)
{
    int wid = threadIdx.x >> 5, lane = threadIdx.x & 31;
    int bn = blockIdx.x * 8 + wid;
    int b = bn / N_, i = bn % N_;

    if (i >= NV_) {                          // padded node: zero row + score
        if (lane < 16)
            *(float4*)(g_xc + (size_t)bn * HIN_ + lane*4) =
                make_float4(0.f, 0.f, 0.f, 0.f);
        if (lane == 0) g_s0[bn] = 0.f;
        return;
    }

    int nnz = g_nnz[bn];
    const unsigned short* nidx = g_nidx + (size_t)bn * CAP_;
    int idx0 = (lane      < nnz) ? nidx[lane]      : 0;
    int idx1 = (lane + 32 < nnz) ? nidx[lane + 32] : 0;
    int idx2 = (lane + 64 < nnz) ? nidx[lane + 64] : 0;

    float es = g_es2[bn];
    const float* ed = g_ed2 + b * N_;
    float p0 = 0.f, p1 = 0.f, p2 = 0.f;
    if (lane < nnz)      { float e = es + ed[idx0]; e = (e>0.f)?e:0.2f*e; p0 = __expf(e); }
    if (lane + 32 < nnz) { float e = es + ed[idx1]; e = (e>0.f)?e:0.2f*e; p1 = __expf(e); }
    if (lane + 64 < nnz) { float e = es + ed[idx2]; e = (e>0.f)?e:0.2f*e; p2 = __expf(e); }
    float sum = p0 + p1 + p2;
#pragma unroll
    for (int off = 16; off; off >>= 1) sum += __shfl_xor_sync(FULLM, sum, off);
    float inv = 1.f / sum;

    int slice = lane >> 4, c16 = lane & 15;
    const __half* base = g_h2h + (size_t)b * N_ * HIN_ + c16 * 4;
    float4 acc = make_float4(0.f, 0.f, 0.f, 0.f);
    int mcnt = (nnz + 1) >> 1;
#pragma unroll 4
    for (int m = 0; m < mcnt; m++) {
        int k = slice + (m << 1);
        int ri = (m >> 4);                    // (2m+slice)>>5 — warp-uniform
        float ps = (ri == 0) ? p0 : ((ri == 1) ? p1 : p2);
        int   is = (ri == 0) ? idx0 : ((ri == 1) ? idx1 : idx2);
        float pv = __shfl_sync(FULLM, ps, k & 31);
        int   jj = __shfl_sync(FULLM, is, k & 31);
        if (k < nnz) {
            uint2 u = *(const uint2*)(base + (size_t)jj * HIN_);
            float2 f0 = __half22float2(*(__half2*)&u.x);
            float2 f1 = __half22float2(*(__half2*)&u.y);
            acc.x += pv*f0.x; acc.y += pv*f0.y; acc.z += pv*f1.x; acc.w += pv*f1.y;
        }
    }
    acc.x += __shfl_xor_sync(FULLM, acc.x, 16);
    acc.y += __shfl_xor_sync(FULLM, acc.y, 16);
    acc.z += __shfl_xor_sync(FULLM, acc.z, 16);
    acc.w += __shfl_xor_sync(FULLM, acc.w, 16);
    float4 v4 = make_float4(acc.x*inv, acc.y*inv, acc.z*inv, acc.w*inv);
    if (lane < 16)
        *(float4*)(g_xc + (size_t)bn * HIN_ + c16*4) = v4;

    float4 a4 = __ldg((const float4*)(aw + c16*4));
    float d = v4.x*a4.x + v4.y*a4.y + v4.z*a4.z + v4.w*a4.w;
#pragma unroll
    for (int off = 1; off < 16; off <<= 1) d += __shfl_xor_sync(FULLM, d, off);
    if (lane == 0) g_s0[bn] = d;
}

// ---------------- kernel 3: softmax over nodes + pooled output -------------
__global__ __launch_bounds__(512) void k_final(
    const float* __restrict__ aw, float* __restrict__ out)
{
    int b = blockIdx.x, t = threadIdx.x;
    int wid = t >> 5, lane = t & 31;
    __shared__ __align__(16) float sc[512];
    __shared__ __align__(16) float red4[32][HIN_];
    __shared__ float wred[16];
    __shared__ float sh_m, sh_inv, sh_rdot;

    if (wid == 0) {
        const float* xr = g_xc + (size_t)b * N_ * HIN_;
        float r = xr[lane] * __ldg(aw + HIN_ + lane)
                + xr[lane + 32] * __ldg(aw + HIN_ + lane + 32);
#pragma unroll
        for (int off = 16; off; off >>= 1) r += __shfl_xor_sync(FULLM, r, off);
        if (lane == 0) sh_rdot = r;
    }
    __syncthreads();
    float rdot = sh_rdot;

    float s = -3e38f;
    if (t < N_) {
        s = g_s0[b * N_ + t];
        if (t < NV_) s += rdot;
        if (s == 0.f) s = NEG_INF_;
        sc[t] = s;
    }
    float m = s;
#pragma unroll
    for (int off = 16; off; off >>= 1) m = fmaxf(m, __shfl_xor_sync(FULLM, m, off));
    if (lane == 0) wred[wid] = m;
    __syncthreads();
    if (t < 32) {
        float mm = (t < 16) ? wred[t] : -3e38f;
#pragma unroll
        for (int off = 8; off; off >>= 1) mm = fmaxf(mm, __shfl_xor_sync(FULLM, mm, off));
        if (t == 0) sh_m = mm;
    }
    __syncthreads();
    m = sh_m;

    float p = (t < N_) ? __expf(sc[t] - m) : 0.f;
    if (t < N_) sc[t] = p;
    float ls = p;
#pragma unroll
    for (int off = 16; off; off >>= 1) ls += __shfl_xor_sync(FULLM, ls, off);
    if (lane == 0) wred[wid] = ls;
    __syncthreads();
    if (t < 32) {
        float ss = (t < 16) ? wred[t] : 0.f;
#pragma unroll
        for (int off = 8; off; off >>= 1) ss += __shfl_xor_sync(FULLM, ss, off);
        if (t == 0) sh_inv = 1.f / ss;
    }
    __syncthreads();
    float inv = sh_inv;

    if (t < N_) out[B_ * HIN_ + b * N_ + t] = p * inv;

    int g = t >> 4, o4 = (t & 15) << 2;
    const float* base = g_xc + (size_t)b * N_ * HIN_ + o4;
    float4 acc = make_float4(0.f, 0.f, 0.f, 0.f);
    for (int n = g; n < N_; n += 32) {
        float w = sc[n];
        float4 hv = *(const float4*)(base + (size_t)n * HIN_);
        acc.x += w*hv.x; acc.y += w*hv.y; acc.z += w*hv.z; acc.w += w*hv.w;
    }
    *(float4*)&red4[g][o4] = acc;
    __syncthreads();
    if (t < HIN_) {
        float tot = 0.f;
#pragma unroll
        for (int k = 0; k < 32; k++) tot += red4[k][t];
        out[b * HIN_ + t] = tot * inv;
    }
}

// ---------------------------------------------------------------------------
extern "C" void kernel_launch(void* const* d_in, const int* in_sizes, int n_in,
                              void* d_out, int out_size)
{
    const float* x       = (const float*)d_in[0];
    const float* A       = (const float*)d_in[1];
    const float* w1      = (const float*)d_in[4];
    const float* a_src1  = (const float*)d_in[5];
    const float* a_dst1  = (const float*)d_in[6];
    const float* w2      = (const float*)d_in[7];
    const float* a_src2  = (const float*)d_in[8];
    const float* a_dst2  = (const float*)d_in[9];
    const float* attn_w  = (const float*)d_in[10];
    float* out = (float*)d_out;

    k_compact   <<<B_ * N_ / 8, 256>>>(A);
    k_proj1     <<<B_ * N_ / 64, 256>>>(x, w1, a_src1, a_dst1);
    k_attn1proj2<<<B_ * N_, 256>>>(w2, a_src2, a_dst2);
    k_attn2     <<<B_ * N_ / 8, 256>>>(attn_w);
    k_final     <<<B_, 512>>>(attn_w, out);
}

// round 17
// speedup vs baseline: 1.7961x; 1.0819x over previous
#include <cuda_runtime.h>
#include <cuda_bf16.h>
#include <cuda_fp16.h>

#define B_    32
#define N_    500
#define NV_   400
#define HIN_  64
#define HID_  16
#define NH_   8
#define HC_   128   // NH*HID
#define CAP_  96
#define STR_  68
#define NEG_INF_ -1e20f
#define FULLM 0xffffffffu

// ---------------- scratch (device globals; 16B-aligned) --------------------
__device__ __align__(16) __half g_h1h [B_*N_*HC_];   // layer-1 proj, fp16 [bn][128]
__device__ float g_es1  [B_*NH_*N_];
__device__ float g_ed1  [B_*NH_*N_];
__device__ __align__(16) __half g_h2h [B_*N_*HIN_];  // fp16 [bn][64]
__device__ float g_es2  [B_*N_];
__device__ float g_ed2  [B_*N_];
__device__ __align__(16) float g_xc   [B_*N_*HIN_];  // fp32 [bn][64]
__device__ float g_s0   [B_*N_];                     // xc . attn_w[0:64]
__device__ unsigned short g_nidx[B_*N_*CAP_];
__device__ int            g_nnz [B_*N_];

// ---------------- kernel 0a: adjacency compaction (standalone, low-reg) ----
__global__ __launch_bounds__(256) void k_compact(const float* __restrict__ A)
{
    int w = threadIdx.x >> 5, lane = threadIdx.x & 31;
    int bn = blockIdx.x * 8 + w;
    const float4* row = (const float4*)(A + (size_t)bn * N_);   // 125 float4
    unsigned short* out = g_nidx + (size_t)bn * CAP_;

    float4 v[4];
#pragma unroll
    for (int r = 0; r < 4; r++) {
        int q = r * 32 + lane;
        v[r] = (q < 125) ? __ldg(row + q) : make_float4(0.f, 0.f, 0.f, 0.f);
    }

    int cnt = 0;
#pragma unroll
    for (int r = 0; r < 4; r++) {
        int q = r * 32 + lane;
        unsigned m4 = (v[r].x > 0.f) | ((v[r].y > 0.f) << 1)
                    | ((v[r].z > 0.f) << 2) | ((v[r].w > 0.f) << 3);
        if (q >= 125) m4 = 0;
        int c4 = __popc(m4);
        int inc = c4;
#pragma unroll
        for (int off = 1; off < 32; off <<= 1) {
            int nb = __shfl_up_sync(FULLM, inc, off);
            if (lane >= off) inc += nb;
        }
        int excl = inc - c4;
        int basej = q << 2;
#pragma unroll
        for (int e = 0; e < 4; e++)
            if (m4 & (1u << e)) {
                int pos = cnt + excl + __popc(m4 & ((1u << e) - 1u));
                if (pos < CAP_) out[pos] = (unsigned short)(basej + e);
            }
        cnt += __shfl_sync(FULLM, inc, 31);
    }
    if (lane == 0) g_nnz[bn] = cnt < CAP_ ? cnt : CAP_;
}

// ---------------- kernel 0b: layer-1 tiled projection (standalone) ---------
__global__ __launch_bounds__(256) void k_proj1(
    const float* __restrict__ x, const float* __restrict__ w1,
    const float* __restrict__ a_src1, const float* __restrict__ a_dst1)
{
    __shared__ __align__(16) float xt[HIN_ * STR_];
    int t = threadIdx.x;
    int gbase = blockIdx.x * 64;

    for (int i = t; i < 1024; i += 256) {
        int row = i >> 4, fg = (i & 15) << 2;
        float4 v = *(const float4*)(x + (size_t)(gbase + row) * HIN_ + fg);
        xt[(fg+0)*STR_ + row] = v.x; xt[(fg+1)*STR_ + row] = v.y;
        xt[(fg+2)*STR_ + row] = v.z; xt[(fg+3)*STR_ + row] = v.w;
    }
    __syncthreads();

    int rt = t >> 4, ct = t & 15;
    int h = ct >> 1, obase = (ct & 1) << 3;
    const float* wb = w1 + (h << 10) + obase;

    float acc[4][8];
#pragma unroll
    for (int a = 0; a < 4; a++)
#pragma unroll
        for (int c = 0; c < 8; c++) acc[a][c] = 0.f;

#pragma unroll 4
    for (int f = 0; f < HIN_; f++) {
        float4 xv = *(float4*)&xt[f*STR_ + rt*4];
        float4 w0 = __ldg((const float4*)(wb + (f << 4)));
        float4 w1v= __ldg((const float4*)(wb + (f << 4) + 4));
        float xr[4] = {xv.x, xv.y, xv.z, xv.w};
        float wr[8] = {w0.x,w0.y,w0.z,w0.w,w1v.x,w1v.y,w1v.z,w1v.w};
#pragma unroll
        for (int a = 0; a < 4; a++)
#pragma unroll
            for (int c = 0; c < 8; c++) acc[a][c] += xr[a] * wr[c];
    }

    float as[8], ad[8];
#pragma unroll
    for (int c = 0; c < 8; c++) {
        as[c] = __ldg(a_src1 + h*HID_ + obase + c);
        ad[c] = __ldg(a_dst1 + h*HID_ + obase + c);
    }
#pragma unroll
    for (int rr = 0; rr < 4; rr++) {
        int gr = gbase + rt*4 + rr;
        int b = gr / N_, n = gr % N_;
        __align__(16) __half2 hp[4];
        hp[0] = __floats2half2_rn(acc[rr][0], acc[rr][1]);
        hp[1] = __floats2half2_rn(acc[rr][2], acc[rr][3]);
        hp[2] = __floats2half2_rn(acc[rr][4], acc[rr][5]);
        hp[3] = __floats2half2_rn(acc[rr][6], acc[rr][7]);
        *(uint4*)(g_h1h + (size_t)gr * HC_ + ct*8) = *(uint4*)hp;
        float ps = 0.f, pd = 0.f;
#pragma unroll
        for (int c = 0; c < 8; c++) { ps += acc[rr][c]*as[c]; pd += acc[rr][c]*ad[c]; }
        ps += __shfl_xor_sync(FULLM, ps, 1);
        pd += __shfl_xor_sync(FULLM, pd, 1);
        if ((ct & 1) == 0) {
            g_es1[(b*NH_ + h) * N_ + n] = ps;
            g_ed1[(b*NH_ + h) * N_ + n] = pd;
        }
    }
}

// ---------------- kernel 1: layer-1 attention + ELU + layer-2 proj ---------
__global__ __launch_bounds__(256) void k_attn1proj2(
    const float* __restrict__ w2,
    const float* __restrict__ a_src2, const float* __restrict__ a_dst2)
{
    int bn = blockIdx.x;
    int b = bn / N_, i = bn % N_;
    __shared__ __align__(16) float red[8][HC_];
    __shared__ __align__(16) float sp[NH_][CAP_];
    __shared__ __align__(16) float hcat[HC_];
    __shared__ __align__(16) float h2s[HIN_];
    __shared__ int   snj[CAP_];
    __shared__ float sinv[NH_];
    int t = threadIdx.x, h = t >> 5, lane = t & 31;
    int nnz = g_nnz[bn];

    const unsigned short* nidx = g_nidx + (size_t)bn * CAP_;
    if (t < nnz) snj[t] = nidx[t];
    __syncthreads();

    float es = g_es1[(b*NH_ + h) * N_ + i];
    const float* ed = g_ed1 + (b*NH_ + h) * N_;
    float sum = 0.f;
    for (int k = lane; k < nnz; k += 32) {
        float e = es + ed[snj[k]];
        e = (e > 0.f) ? e : 0.2f * e;
        float p = __expf(e);
        sp[h][k] = p;
        sum += p;
    }
#pragma unroll
    for (int off = 16; off; off >>= 1) sum += __shfl_xor_sync(FULLM, sum, off);
    if (lane == 0) sinv[h] = 1.f / sum;
    __syncthreads();

    int slice = t >> 5, q4 = (t & 31) << 2, hh = q4 >> 4;
    const __half* base = g_h1h + (size_t)b * N_ * HC_ + q4;
    float4 acc = make_float4(0.f, 0.f, 0.f, 0.f);
    for (int k = slice; k < nnz; k += 8) {
        float w = sp[hh][k];
        uint2 u = *(const uint2*)(base + (size_t)snj[k] * HC_);
        float2 f0 = __half22float2(*(__half2*)&u.x);
        float2 f1 = __half22float2(*(__half2*)&u.y);
        acc.x += w*f0.x; acc.y += w*f0.y; acc.z += w*f1.x; acc.w += w*f1.y;
    }
    *(float4*)&red[slice][q4] = acc;
    __syncthreads();

    if (t < HC_) {
        float s = 0.f;
#pragma unroll
        for (int s8 = 0; s8 < 8; s8++) s += red[s8][t];
        float v = s * sinv[t >> 4];
        v = (v > 0.f) ? v : (__expf(v) - 1.f);
        hcat[t] = v;
    }
    __syncthreads();

    {
        int o = t & 63, g = t >> 6;
        const float* wv = w2 + (g << 5) * HIN_ + o;
        float a2 = 0.f;
#pragma unroll 8
        for (int f = 0; f < 32; f++) a2 += hcat[(g << 5) + f] * wv[f * HIN_];
        red[g][o] = a2;
    }
    __syncthreads();
    if (t < HIN_) {
        float hv = red[0][t] + red[1][t] + red[2][t] + red[3][t];
        h2s[t] = hv;
        g_h2h[(size_t)bn * HIN_ + t] = __float2half_rn(hv);
    }
    __syncthreads();
    if (t < 32) {
        float v0 = h2s[t], v1 = h2s[t + 32];
        float ps = v0 * __ldg(a_src2 + t) + v1 * __ldg(a_src2 + t + 32);
        float pd = v0 * __ldg(a_dst2 + t) + v1 * __ldg(a_dst2 + t + 32);
#pragma unroll
        for (int off = 16; off; off >>= 1) {
            ps += __shfl_xor_sync(FULLM, ps, off);
            pd += __shfl_xor_sync(FULLM, pd, off);
        }
        if (t == 0) { g_es2[bn] = ps; g_ed2[bn] = pd; }
    }
}

// ---------------- kernel 2: layer-2 attention + score dot ------------------
// Warp per row. Gather loop split into 3 fixed-register ranges (no selects).
__global__ __launch_bounds__(256) void k_attn2(const float* __restrict__ aw)
{
    int wid = threadIdx.x >> 5, lane = threadIdx.x & 31;
    int bn = blockIdx.x * 8 + wid;
    int b = bn / N_, i = bn % N_;

    if (i >= NV_) {
        if (lane < 16)
            *(float4*)(g_xc + (size_t)bn * HIN_ + lane*4) =
                make_float4(0.f, 0.f, 0.f, 0.f);
        if (lane == 0) g_s0[bn] = 0.f;
        return;
    }

    int nnz = g_nnz[bn];
    const unsigned short* nidx = g_nidx + (size_t)bn * CAP_;
    int idx0 = (lane      < nnz) ? nidx[lane]      : 0;
    int idx1 = (lane + 32 < nnz) ? nidx[lane + 32] : 0;
    int idx2 = (lane + 64 < nnz) ? nidx[lane + 64] : 0;

    float es = g_es2[bn];
    const float* ed = g_ed2 + b * N_;
    float p0 = 0.f, p1 = 0.f, p2 = 0.f;
    if (lane < nnz)      { float e = es + ed[idx0]; e = (e>0.f)?e:0.2f*e; p0 = __expf(e); }
    if (lane + 32 < nnz) { float e = es + ed[idx1]; e = (e>0.f)?e:0.2f*e; p1 = __expf(e); }
    if (lane + 64 < nnz) { float e = es + ed[idx2]; e = (e>0.f)?e:0.2f*e; p2 = __expf(e); }
    float sum = p0 + p1 + p2;
#pragma unroll
    for (int off = 16; off; off >>= 1) sum += __shfl_xor_sync(FULLM, sum, off);
    float inv = 1.f / sum;

    int slice = lane >> 4, c16 = lane & 15;
    const __half* base = g_h2h + (size_t)b * N_ * HIN_ + c16 * 4;
    float4 acc = make_float4(0.f, 0.f, 0.f, 0.f);
    int mcnt = (nnz + 1) >> 1;
    int m1 = mcnt < 16 ? mcnt : 16;
    int m2 = mcnt < 32 ? mcnt : 32;

#pragma unroll 4
    for (int m = 0; m < m1; m++) {            // k in [0,32): p0/idx0
        int k = slice + (m << 1);
        float pv = __shfl_sync(FULLM, p0, k);
        int   jj = __shfl_sync(FULLM, idx0, k);
        if (k < nnz) {
            uint2 u = *(const uint2*)(base + (size_t)jj * HIN_);
            float2 f0 = __half22float2(*(__half2*)&u.x);
            float2 f1 = __half22float2(*(__half2*)&u.y);
            acc.x += pv*f0.x; acc.y += pv*f0.y; acc.z += pv*f1.x; acc.w += pv*f1.y;
        }
    }
#pragma unroll 4
    for (int m = 16; m < m2; m++) {           // k in [32,64): p1/idx1
        int k = slice + (m << 1);
        float pv = __shfl_sync(FULLM, p1, k & 31);
        int   jj = __shfl_sync(FULLM, idx1, k & 31);
        if (k < nnz) {
            uint2 u = *(const uint2*)(base + (size_t)jj * HIN_);
            float2 f0 = __half22float2(*(__half2*)&u.x);
            float2 f1 = __half22float2(*(__half2*)&u.y);
            acc.x += pv*f0.x; acc.y += pv*f0.y; acc.z += pv*f1.x; acc.w += pv*f1.y;
        }
    }
    for (int m = 32; m < mcnt; m++) {         // k in [64,96): p2/idx2
        int k = slice + (m << 1);
        float pv = __shfl_sync(FULLM, p2, k & 31);
        int   jj = __shfl_sync(FULLM, idx2, k & 31);
        if (k < nnz) {
            uint2 u = *(const uint2*)(base + (size_t)jj * HIN_);
            float2 f0 = __half22float2(*(__half2*)&u.x);
            float2 f1 = __half22float2(*(__half2*)&u.y);
            acc.x += pv*f0.x; acc.y += pv*f0.y; acc.z += pv*f1.x; acc.w += pv*f1.y;
        }
    }

    acc.x += __shfl_xor_sync(FULLM, acc.x, 16);
    acc.y += __shfl_xor_sync(FULLM, acc.y, 16);
    acc.z += __shfl_xor_sync(FULLM, acc.z, 16);
    acc.w += __shfl_xor_sync(FULLM, acc.w, 16);
    float4 v4 = make_float4(acc.x*inv, acc.y*inv, acc.z*inv, acc.w*inv);
    if (lane < 16)
        *(float4*)(g_xc + (size_t)bn * HIN_ + c16*4) = v4;

    float4 a4 = __ldg((const float4*)(aw + c16*4));
    float d = v4.x*a4.x + v4.y*a4.y + v4.z*a4.z + v4.w*a4.w;
#pragma unroll
    for (int off = 1; off < 16; off <<= 1) d += __shfl_xor_sync(FULLM, d, off);
    if (lane == 0) g_s0[bn] = d;
}

// ---------------- kernel 3: softmax + pooled, channel-split 4x -------------
// 128 blocks = (graph b, channel-quarter q). Each block recomputes the cheap
// node softmax from g_s0, then pools ONLY its 16 channels (disjoint outputs,
// no partials kernel). q==0 blocks also write the attn output.
__global__ __launch_bounds__(512) void k_final(
    const float* __restrict__ aw, float* __restrict__ out)
{
    int b = blockIdx.x >> 2, q = blockIdx.x & 3;
    int t = threadIdx.x;
    int wid = t >> 5, lane = t & 31;
    __shared__ __align__(16) float sc[512];
    __shared__ __align__(16) float red16[32][16];
    __shared__ float wred[16];
    __shared__ float sh_m, sh_inv, sh_rdot;

    // rdot = xc[b,0,:] . aw[64:128]  (warp 0)
    if (wid == 0) {
        const float* xr = g_xc + (size_t)b * N_ * HIN_;
        float r = xr[lane] * __ldg(aw + HIN_ + lane)
                + xr[lane + 32] * __ldg(aw + HIN_ + lane + 32);
#pragma unroll
        for (int off = 16; off; off >>= 1) r += __shfl_xor_sync(FULLM, r, off);
        if (lane == 0) sh_rdot = r;
    }
    __syncthreads();
    float rdot = sh_rdot;

    // scores (one node per thread; 500 < 512)
    float s = -3e38f;
    if (t < N_) {
        s = g_s0[b * N_ + t];
        if (t < NV_) s += rdot;
        if (s == 0.f) s = NEG_INF_;
        sc[t] = s;
    }
    float m = s;
#pragma unroll
    for (int off = 16; off; off >>= 1) m = fmaxf(m, __shfl_xor_sync(FULLM, m, off));
    if (lane == 0) wred[wid] = m;
    __syncthreads();
    if (t < 32) {
        float mm = (t < 16) ? wred[t] : -3e38f;
#pragma unroll
        for (int off = 8; off; off >>= 1) mm = fmaxf(mm, __shfl_xor_sync(FULLM, mm, off));
        if (t == 0) sh_m = mm;
    }
    __syncthreads();
    m = sh_m;

    float p = (t < N_) ? __expf(sc[t] - m) : 0.f;
    if (t < N_) sc[t] = p;
    float ls = p;
#pragma unroll
    for (int off = 16; off; off >>= 1) ls += __shfl_xor_sync(FULLM, ls, off);
    if (lane == 0) wred[wid] = ls;
    __syncthreads();
    if (t < 32) {
        float ss = (t < 16) ? wred[t] : 0.f;
#pragma unroll
        for (int off = 8; off; off >>= 1) ss += __shfl_xor_sync(FULLM, ss, off);
        if (t == 0) sh_inv = 1.f / ss;
    }
    __syncthreads();
    float inv = sh_inv;

    if (q == 0 && t < N_) out[B_ * HIN_ + b * N_ + t] = p * inv;

    // pooled channels [q*16, q*16+16): 32 n-slices x 16 channels (scalar)
    int g = t >> 4, ch = t & 15;
    const float* base = g_xc + (size_t)b * N_ * HIN_ + q * 16 + ch;
    float acc = 0.f;
    for (int n = g; n < N_; n += 32)
        acc += sc[n] * base[(size_t)n * HIN_];
    red16[g][ch] = acc;
    __syncthreads();
    if (t < 16) {
        float tot = 0.f;
#pragma unroll
        for (int k = 0; k < 32; k++) tot += red16[k][t];
        out[b * HIN_ + q * 16 + t] = tot * inv;
    }
}

// ---------------------------------------------------------------------------
extern "C" void kernel_launch(void* const* d_in, const int* in_sizes, int n_in,
                              void* d_out, int out_size)
{
    const float* x       = (const float*)d_in[0];
    const float* A       = (const float*)d_in[1];
    const float* w1      = (const float*)d_in[4];
    const float* a_src1  = (const float*)d_in[5];
    const float* a_dst1  = (const float*)d_in[6];
    const float* w2      = (const float*)d_in[7];
    const float* a_src2  = (const float*)d_in[8];
    const float* a_dst2  = (const float*)d_in[9];
    const float* attn_w  = (const float*)d_in[10];
    float* out = (float*)d_out;

    k_compact   <<<B_ * N_ / 8, 256>>>(A);
    k_proj1     <<<B_ * N_ / 64, 256>>>(x, w1, a_src1, a_dst1);
    k_attn1proj2<<<B_ * N_, 256>>>(w2, a_src2, a_dst2);
    k_attn2     <<<B_ * N_ / 8, 256>>>(attn_w);
    k_final     <<<B_ * 4, 512>>>(attn_w, out);
}